// round 1
// baseline (speedup 1.0000x reference)
#include <cuda_runtime.h>
#include <math.h>

// Problem constants (fixed by the dataset)
#define Bn   4
#define Sn   1024
#define Dn   1024
#define Hn   16
#define DHn  64
#define DFFn 4096
#define TOK  (Bn*Sn)          // 4096
#define EPSF 1e-5f
#define NEGF (-1e20f)

// ---------------- static device workspaces (no allocation allowed) ----------------
__device__ float g_q [TOK*Dn];
__device__ float g_k [TOK*Dn];
__device__ float g_v [TOK*Dn];
__device__ float g_t1[TOK*Dn];
__device__ float g_t2[TOK*Dn];
__device__ float g_t3[TOK*Dn];
__device__ float g_ff[TOK*DFFn];
__device__ float g_cs[Bn*Hn*Sn];

// ---------------- tiled SGEMM: C[M,N] = A[M,K] @ W[N,K]^T (+bias)(+relu) ----------
// M,N multiples of 128; K multiple of 8. 256 threads, 8x8 per thread.
__global__ void __launch_bounds__(256, 2)
sgemm_kernel(const float* __restrict__ A, const float* __restrict__ W,
             const float* __restrict__ bias, float* __restrict__ C,
             int M, int N, int K, int act)
{
    __shared__ float As[8][132];
    __shared__ float Bs[8][132];

    const int tid = threadIdx.x;
    const int m0 = blockIdx.y * 128;
    const int n0 = blockIdx.x * 128;
    const int tm = (tid >> 4) * 8;   // 0..120
    const int tn = (tid & 15) * 8;   // 0..120

    const int lr = tid >> 1;         // 0..127
    const int lc = (tid & 1) * 4;    // 0 or 4

    const float* Ap = A + (size_t)(m0 + lr) * K + lc;
    const float* Wp = W + (size_t)(n0 + lr) * K + lc;

    float acc[8][8];
#pragma unroll
    for (int i = 0; i < 8; i++)
#pragma unroll
        for (int j = 0; j < 8; j++) acc[i][j] = 0.f;

    for (int k0 = 0; k0 < K; k0 += 8) {
        float4 av = *(const float4*)(Ap + k0);
        float4 wv = *(const float4*)(Wp + k0);
        As[lc + 0][lr] = av.x; As[lc + 1][lr] = av.y;
        As[lc + 2][lr] = av.z; As[lc + 3][lr] = av.w;
        Bs[lc + 0][lr] = wv.x; Bs[lc + 1][lr] = wv.y;
        Bs[lc + 2][lr] = wv.z; Bs[lc + 3][lr] = wv.w;
        __syncthreads();

#pragma unroll
        for (int kk = 0; kk < 8; kk++) {
            float a[8], b[8];
            float4 a0 = *(const float4*)&As[kk][tm];
            float4 a1 = *(const float4*)&As[kk][tm + 4];
            float4 b0 = *(const float4*)&Bs[kk][tn];
            float4 b1 = *(const float4*)&Bs[kk][tn + 4];
            a[0]=a0.x; a[1]=a0.y; a[2]=a0.z; a[3]=a0.w;
            a[4]=a1.x; a[5]=a1.y; a[6]=a1.z; a[7]=a1.w;
            b[0]=b0.x; b[1]=b0.y; b[2]=b0.z; b[3]=b0.w;
            b[4]=b1.x; b[5]=b1.y; b[6]=b1.z; b[7]=b1.w;
#pragma unroll
            for (int i = 0; i < 8; i++)
#pragma unroll
                for (int j = 0; j < 8; j++)
                    acc[i][j] = fmaf(a[i], b[j], acc[i][j]);
        }
        __syncthreads();
    }

    float bs[8];
#pragma unroll
    for (int j = 0; j < 8; j++) bs[j] = bias ? bias[n0 + tn + j] : 0.f;

#pragma unroll
    for (int i = 0; i < 8; i++) {
        size_t crow = (size_t)(m0 + tm + i) * N + n0 + tn;
#pragma unroll
        for (int jj = 0; jj < 2; jj++) {
            float4 r;
            float v0 = acc[i][jj*4+0] + bs[jj*4+0];
            float v1 = acc[i][jj*4+1] + bs[jj*4+1];
            float v2 = acc[i][jj*4+2] + bs[jj*4+2];
            float v3 = acc[i][jj*4+3] + bs[jj*4+3];
            if (act) { v0 = fmaxf(v0, 0.f); v1 = fmaxf(v1, 0.f);
                       v2 = fmaxf(v2, 0.f); v3 = fmaxf(v3, 0.f); }
            r.x = v0; r.y = v1; r.z = v2; r.w = v3;
            *(float4*)&C[crow + jj*4] = r;
        }
    }
}

// ---------------- per-head layernorm over DH=64, in-place, one warp per row -------
__global__ void ln_head_kernel(float* __restrict__ x,
                               const float* __restrict__ g, const float* __restrict__ b,
                               int rows)
{
    int row = blockIdx.x * 8 + (threadIdx.x >> 5);
    int lane = threadIdx.x & 31;
    if (row >= rows) return;
    float* p = x + (size_t)row * 64;
    float v0 = p[lane], v1 = p[lane + 32];
    float s = v0 + v1;
#pragma unroll
    for (int off = 16; off; off >>= 1) s += __shfl_xor_sync(0xffffffffu, s, off);
    float mu = s * (1.f / 64.f);
    float d0 = v0 - mu, d1 = v1 - mu;
    float q = d0 * d0 + d1 * d1;
#pragma unroll
    for (int off = 16; off; off >>= 1) q += __shfl_xor_sync(0xffffffffu, q, off);
    float r = rsqrtf(q * (1.f / 64.f) + EPSF);
    p[lane]      = d0 * r * g[lane]      + b[lane];
    p[lane + 32] = d1 * r * g[lane + 32] + b[lane + 32];
}

// ---------------- block reduction helper (sum pair) for 256-thread blocks ---------
__device__ __forceinline__ float2 blockReduce2(float a, float b)
{
    __shared__ float sa[8], sb[8];
    int lane = threadIdx.x & 31, w = threadIdx.x >> 5;
#pragma unroll
    for (int off = 16; off; off >>= 1) {
        a += __shfl_xor_sync(0xffffffffu, a, off);
        b += __shfl_xor_sync(0xffffffffu, b, off);
    }
    __syncthreads();                 // protect smem from previous call's readers
    if (lane == 0) { sa[w] = a; sb[w] = b; }
    __syncthreads();
    float ra = 0.f, rb = 0.f;
#pragma unroll
    for (int i = 0; i < 8; i++) { ra += sa[i]; rb += sb[i]; }
    return make_float2(ra, rb);
}

// ---------------- layernorm over D=1024 (+optional residual), block per row -------
__global__ void ln1024_kernel(const float* __restrict__ in, const float* __restrict__ res,
                              const float* __restrict__ g, const float* __restrict__ b,
                              float* __restrict__ out)
{
    int row = blockIdx.x, tid = threadIdx.x;
    size_t base = (size_t)row * 1024 + tid * 4;
    float4 v = *(const float4*)(in + base);
    float x[4] = { v.x, v.y, v.z, v.w };
    if (res) {
        float4 rv = *(const float4*)(res + base);
        x[0] += rv.x; x[1] += rv.y; x[2] += rv.z; x[3] += rv.w;
    }
    float sa = 0.f, sb = 0.f;
#pragma unroll
    for (int i = 0; i < 4; i++) { sa += x[i]; sb += x[i] * x[i]; }
    float2 r = blockReduce2(sa, sb);
    float mu = r.x * (1.f / 1024.f);
    float var = r.y * (1.f / 1024.f) - mu * mu;
    float rs = rsqrtf(var + EPSF);
    float4 g4 = *(const float4*)(g + tid * 4);
    float4 b4 = *(const float4*)(b + tid * 4);
    float4 o;
    o.x = (x[0] - mu) * rs * g4.x + b4.x;
    o.y = (x[1] - mu) * rs * g4.y + b4.y;
    o.z = (x[2] - mu) * rs * g4.z + b4.z;
    o.w = (x[3] - mu) * rs * g4.w + b4.w;
    *(float4*)(out + base) = o;
}

// ---------------- fused gate: LN(s), LN(h), sigmoid gate, LN(mix) ------------------
__global__ void gate_kernel(const float* __restrict__ sp, const float* __restrict__ hp,
                            const float* __restrict__ bf,
                            const float* __restrict__ gg, const float* __restrict__ gb,
                            float* __restrict__ out)
{
    int row = blockIdx.x, tid = threadIdx.x;
    size_t base = (size_t)row * 1024 + tid * 4;
    float4 sv = *(const float4*)(sp + base);
    float4 hv = *(const float4*)(hp + base);
    float s[4] = { sv.x, sv.y, sv.z, sv.w };
    float h[4] = { hv.x, hv.y, hv.z, hv.w };

    float sa = 0.f, sb = 0.f;
#pragma unroll
    for (int i = 0; i < 4; i++) { sa += s[i]; sb += s[i] * s[i]; }
    float2 r = blockReduce2(sa, sb);
    float mus = r.x * (1.f / 1024.f);
    float rs = rsqrtf(r.y * (1.f / 1024.f) - mus * mus + EPSF);

    sa = 0.f; sb = 0.f;
#pragma unroll
    for (int i = 0; i < 4; i++) { sa += h[i]; sb += h[i] * h[i]; }
    r = blockReduce2(sa, sb);
    float muh = r.x * (1.f / 1024.f);
    float rh = rsqrtf(r.y * (1.f / 1024.f) - muh * muh + EPSF);

    float4 g4 = *(const float4*)(gg + tid * 4);
    float4 b4 = *(const float4*)(gb + tid * 4);
    float4 f4 = *(const float4*)(bf + tid * 4);
    float gA[4] = { g4.x, g4.y, g4.z, g4.w };
    float bA[4] = { b4.x, b4.y, b4.z, b4.w };
    float fA[4] = { f4.x, f4.y, f4.z, f4.w };

    float t[4];
    sa = 0.f; sb = 0.f;
#pragma unroll
    for (int i = 0; i < 4; i++) {
        float sf = (s[i] - mus) * rs * gA[i] + bA[i];
        float hf = (h[i] - muh) * rh * gA[i] + bA[i];
        float f = 1.f / (1.f + expf(-(sf + hf + fA[i])));
        float ti = f * sf + (1.f - f) * hf;
        t[i] = ti; sa += ti; sb += ti * ti;
    }
    r = blockReduce2(sa, sb);
    float mut = r.x * (1.f / 1024.f);
    float rt = rsqrtf(r.y * (1.f / 1024.f) - mut * mut + EPSF);
    float4 o;
    o.x = (t[0] - mut) * rt * gA[0] + bA[0];
    o.y = (t[1] - mut) * rt * gA[1] + bA[1];
    o.z = (t[2] - mut) * rt * gA[2] + bA[2];
    o.w = (t[3] - mut) * rt * gA[3] + bA[3];
    *(float4*)(out + base) = o;
}

// ---------------- attention softmax column-sum ------------------------------------
// colsum[n,h,l] = sum_q softmax_k(pre[n,h,q,:])[l]
// pre = qk/32 + mq*mk*dir + (-|q-k|),  dir = 0 if q>k else -1e20.
// Block: 8 warps = 8 q rows; grid (S/8, H, B). Scores kept in registers (32/lane).
__global__ void __launch_bounds__(256)
attn_colsum_kernel(const float* __restrict__ qln, const float* __restrict__ kln,
                   const float* __restrict__ mask, float* __restrict__ colsum)
{
    __shared__ float Ks[128][65];
    __shared__ float qs[8][64];
    __shared__ float cs[1024];

    const int tid = threadIdx.x, lane = tid & 31, w = tid >> 5;
    const int n = blockIdx.z, h = blockIdx.y, q0 = blockIdx.x * 8;

    for (int i = tid; i < 1024; i += 256) cs[i] = 0.f;
    for (int i = tid; i < 8 * 64; i += 256) {
        int rr = i >> 6, d = i & 63;
        qs[rr][d] = qln[(((size_t)n * Sn + q0 + rr) * Hn + h) * 64 + d];
    }
    __syncthreads();

    const int q = q0 + w;
    const float mq = mask[n * Sn + q];
    float s[32];

#pragma unroll
    for (int t = 0; t < 8; t++) {
        for (int i = tid; i < 2048; i += 256) {
            int rr = i >> 4, c4 = (i & 15) * 4;
            float4 kv = *(const float4*)&kln[(((size_t)n * Sn + t * 128 + rr) * Hn + h) * 64 + c4];
            Ks[rr][c4 + 0] = kv.x; Ks[rr][c4 + 1] = kv.y;
            Ks[rr][c4 + 2] = kv.z; Ks[rr][c4 + 3] = kv.w;
        }
        __syncthreads();

        float a0 = 0.f, a1 = 0.f, a2 = 0.f, a3 = 0.f;
#pragma unroll 8
        for (int d = 0; d < 64; d++) {
            float qb = qs[w][d];
            a0 = fmaf(qb, Ks[lane][d], a0);
            a1 = fmaf(qb, Ks[lane + 32][d], a1);
            a2 = fmaf(qb, Ks[lane + 64][d], a2);
            a3 = fmaf(qb, Ks[lane + 96][d], a3);
        }
        float acc[4] = { a0, a1, a2, a3 };
#pragma unroll
        for (int j = 0; j < 4; j++) {
            int kg = t * 128 + lane + 32 * j;
            float mk = mask[n * Sn + kg];
            float fm = mq * mk * ((q > kg) ? 0.f : NEGF);
            float dist = -fabsf((float)(q - kg));
            s[t * 4 + j] = (acc[j] * 0.03125f + fm) + dist;
        }
        __syncthreads();
    }

    // row softmax over the 32 register scores (1024 entries across the warp)
    float m = s[0];
#pragma unroll
    for (int i = 1; i < 32; i++) m = fmaxf(m, s[i]);
#pragma unroll
    for (int off = 16; off; off >>= 1) m = fmaxf(m, __shfl_xor_sync(0xffffffffu, m, off));
    float Z = 0.f;
#pragma unroll
    for (int i = 0; i < 32; i++) { s[i] = expf(s[i] - m); Z += s[i]; }
#pragma unroll
    for (int off = 16; off; off >>= 1) Z += __shfl_xor_sync(0xffffffffu, Z, off);
    float invZ = 1.f / Z;

#pragma unroll
    for (int i = 0; i < 32; i++) {
        int kg = (i >> 2) * 128 + lane + 32 * (i & 3);
        atomicAdd(&cs[kg], s[i] * invZ);
    }
    __syncthreads();

    float* dst = colsum + ((size_t)n * Hn + h) * Sn;
    for (int i = tid; i < 1024; i += 256) atomicAdd(&dst[i], cs[i]);
}

// ---------------- elementwise: attn_out = v_ln * colsum ---------------------------
__global__ void scale_v_kernel(const float* __restrict__ vln, const float* __restrict__ colsum,
                               float* __restrict__ out)
{
    int idx = blockIdx.x * blockDim.x + threadIdx.x;   // TOK*D = 4194304 threads
    int token = idx >> 10;          // /D
    int n = token >> 10;            // /S
    int sidx = token & 1023;
    int h = (idx >> 6) & 15;
    out[idx] = vln[idx] * colsum[(((size_t)n * Hn + h) << 10) + sidx];
}

__global__ void zero_kernel(float* __restrict__ p, int n)
{
    int i = blockIdx.x * blockDim.x + threadIdx.x;
    if (i < n) p[i] = 0.f;
}

// ---------------- host orchestration ----------------------------------------------
extern "C" void kernel_launch(void* const* d_in, const int* in_sizes, int n_in,
                              void* d_out, int out_size)
{
    const float* x     = (const float*)d_in[0];
    const float* mask  = (const float*)d_in[1];
    const float* Wq    = (const float*)d_in[2];
    const float* Wk    = (const float*)d_in[3];
    const float* Wv    = (const float*)d_in[4];
    const float* ln1g  = (const float*)d_in[5];
    const float* ln1b  = (const float*)d_in[6];
    const float* Wo    = (const float*)d_in[7];
    const float* bo    = (const float*)d_in[8];
    const float* ln2g  = (const float*)d_in[9];
    const float* ln2b  = (const float*)d_in[10];
    const float* Ws    = (const float*)d_in[11];
    const float* Wh    = (const float*)d_in[12];
    const float* bf    = (const float*)d_in[13];
    const float* lnfgg = (const float*)d_in[14];
    const float* lnfgb = (const float*)d_in[15];
    const float* Wp1   = (const float*)d_in[16];
    const float* bp1   = (const float*)d_in[17];
    const float* Wp2   = (const float*)d_in[18];
    const float* bp2   = (const float*)d_in[19];
    const float* lnffg = (const float*)d_in[20];
    const float* lnffb = (const float*)d_in[21];
    float* out = (float*)d_out;

    float *q, *k, *v, *t1, *t2, *t3, *ff, *cs;
    cudaGetSymbolAddress((void**)&q,  g_q);
    cudaGetSymbolAddress((void**)&k,  g_k);
    cudaGetSymbolAddress((void**)&v,  g_v);
    cudaGetSymbolAddress((void**)&t1, g_t1);
    cudaGetSymbolAddress((void**)&t2, g_t2);
    cudaGetSymbolAddress((void**)&t3, g_t3);
    cudaGetSymbolAddress((void**)&ff, g_ff);
    cudaGetSymbolAddress((void**)&cs, g_cs);

    dim3 gD(Dn / 128, TOK / 128);        // (8, 32)
    dim3 gF(DFFn / 128, TOK / 128);      // (32, 32)

    // QKV projections
    sgemm_kernel<<<gD, 256>>>(x, Wq, nullptr, q, TOK, Dn, Dn, 0);
    sgemm_kernel<<<gD, 256>>>(x, Wk, nullptr, k, TOK, Dn, Dn, 0);
    sgemm_kernel<<<gD, 256>>>(x, Wv, nullptr, v, TOK, Dn, Dn, 0);

    // per-head LN of q,k,v (in place)
    ln_head_kernel<<<TOK * Hn / 8, 256>>>(q, ln1g, ln1b, TOK * Hn);
    ln_head_kernel<<<TOK * Hn / 8, 256>>>(k, ln1g, ln1b, TOK * Hn);
    ln_head_kernel<<<TOK * Hn / 8, 256>>>(v, ln1g, ln1b, TOK * Hn);

    // attention softmax column sums
    zero_kernel<<<(Bn * Hn * Sn) / 256, 256>>>(cs, Bn * Hn * Sn);
    attn_colsum_kernel<<<dim3(Sn / 8, Hn, Bn), 256>>>(q, k, mask, cs);

    // attn_out = v_ln * colsum  (into q buffer)
    scale_v_kernel<<<(TOK * Dn) / 256, 256>>>(v, cs, q);

    // output projection + LN -> h (in t1)
    sgemm_kernel<<<gD, 256>>>(q, Wo, bo, t1, TOK, Dn, Dn, 0);
    ln1024_kernel<<<TOK, 256>>>(t1, nullptr, ln2g, ln2b, t1);

    // fusion gate
    sgemm_kernel<<<gD, 256>>>(x,  Ws, nullptr, t2, TOK, Dn, Dn, 0);
    sgemm_kernel<<<gD, 256>>>(t1, Wh, nullptr, t3, TOK, Dn, Dn, 0);
    gate_kernel<<<TOK, 256>>>(t2, t3, bf, lnfgg, lnfgb, k);   // g -> k buffer

    // FFN
    sgemm_kernel<<<gF, 256>>>(k, Wp1, bp1, ff, TOK, DFFn, Dn, 1);     // relu
    sgemm_kernel<<<gD, 256>>>(ff, Wp2, bp2, t3, TOK, Dn, DFFn, 0);

    // final residual + LN
    ln1024_kernel<<<TOK, 256>>>(t3, k, lnffg, lnffb, out);
}

// round 4
// speedup vs baseline: 2.5106x; 2.5106x over previous
#include <cuda_runtime.h>
#include <math.h>
#include <stdint.h>

// Problem constants
#define Bn   4
#define Sn   1024
#define Dn   1024
#define Hn   16
#define DHn  64
#define DFFn 4096
#define TOK  (Bn*Sn)          // 4096
#define EPSF 1e-5f
#define NEGF (-1e20f)

// ---------------- static device workspaces ----------------
__device__ float g_q [TOK*Dn];
__device__ float g_k [TOK*Dn];
__device__ float g_v [TOK*Dn];
__device__ float g_t1[TOK*Dn];
__device__ float g_t2[TOK*Dn];
__device__ float g_t3[TOK*Dn];
__device__ float g_ff[TOK*DFFn];
__device__ float g_cs[Bn*Hn*Sn];
__device__ float g_sc[67108864];   // B*H*S*S scores (268MB)

// ---------------- helpers ----------------
__device__ __forceinline__ uint32_t f2tf(float x){
    uint32_t r; asm volatile("cvt.rn.tf32.f32 %0, %1;" : "=r"(r) : "f"(x)); return r;
}
__device__ __forceinline__ void mma_16n8k8(float* c, const uint32_t* a, const uint32_t* b){
    asm volatile(
        "mma.sync.aligned.m16n8k8.row.col.f32.tf32.tf32.f32 "
        "{%0,%1,%2,%3}, {%4,%5,%6,%7}, {%8,%9}, {%0,%1,%2,%3};"
        : "+f"(c[0]), "+f"(c[1]), "+f"(c[2]), "+f"(c[3])
        : "r"(a[0]), "r"(a[1]), "r"(a[2]), "r"(a[3]), "r"(b[0]), "r"(b[1]));
}

// ---------------- tf32 mma.sync GEMM ----------------
// C[M,N] = A[M,K] @ W[N,K]^T (+bias)(+relu); M,N mult of 128, K mult of 16.
// grid = (N/128, M/128, batches); z1=z/zdiv, z2=z%zdiv give batch offsets.
// Block 256 thr (8 warps, 2x4), warp tile 64x32, BK=16, double-buffered smem.
__global__ void __launch_bounds__(256, 2)
gemm_mma(const float* __restrict__ A, const float* __restrict__ W,
         const float* __restrict__ bias, float* __restrict__ C,
         int K, int lda, int ldb, int ldc, int act, int zdiv,
         long long aS1, long long aS2, long long bS1, long long bS2,
         long long cS1, long long cS2)
{
    __shared__ uint32_t As[2][16][136];
    __shared__ uint32_t Bs[2][16][136];

    const int tid = threadIdx.x, lane = tid & 31, wid = tid >> 5;
    const int wm = wid & 1, wn = wid >> 1;          // warp grid 2 x 4
    const int ml = lane >> 2, cl = lane & 3;
    const int z1 = blockIdx.z / zdiv, z2 = blockIdx.z % zdiv;

    A += (size_t)blockIdx.y * 128 * lda + (size_t)z1 * aS1 + (size_t)z2 * aS2;
    W += (size_t)blockIdx.x * 128 * ldb + (size_t)z1 * bS1 + (size_t)z2 * bS2;
    C += (size_t)z1 * cS1 + (size_t)z2 * cS2;

    const int r0 = tid >> 1;                // tile row 0..127
    const int kb = (tid & 1) * 8;           // k sub-block 0 or 8
    const float* Ap = A + (size_t)r0 * lda + kb;
    const float* Wp = W + (size_t)r0 * ldb + kb;

    float acc[4][4][4];
#pragma unroll
    for (int i = 0; i < 4; i++)
#pragma unroll
        for (int j = 0; j < 4; j++)
#pragma unroll
            for (int r = 0; r < 4; r++) acc[i][j][r] = 0.f;

    const int T = K >> 4;

    float4 a0 = *(const float4*)(Ap);
    float4 a1 = *(const float4*)(Ap + 4);
    float4 b0 = *(const float4*)(Wp);
    float4 b1 = *(const float4*)(Wp + 4);

#define STS_TILE(buf) do { \
    As[buf][kb+0][r0] = f2tf(a0.x); As[buf][kb+1][r0] = f2tf(a0.y); \
    As[buf][kb+2][r0] = f2tf(a0.z); As[buf][kb+3][r0] = f2tf(a0.w); \
    As[buf][kb+4][r0] = f2tf(a1.x); As[buf][kb+5][r0] = f2tf(a1.y); \
    As[buf][kb+6][r0] = f2tf(a1.z); As[buf][kb+7][r0] = f2tf(a1.w); \
    Bs[buf][kb+0][r0] = f2tf(b0.x); Bs[buf][kb+1][r0] = f2tf(b0.y); \
    Bs[buf][kb+2][r0] = f2tf(b0.z); Bs[buf][kb+3][r0] = f2tf(b0.w); \
    Bs[buf][kb+4][r0] = f2tf(b1.x); Bs[buf][kb+5][r0] = f2tf(b1.y); \
    Bs[buf][kb+6][r0] = f2tf(b1.z); Bs[buf][kb+7][r0] = f2tf(b1.w); \
} while(0)

    STS_TILE(0);
    __syncthreads();

#pragma unroll 1
    for (int t = 0; t < T; t++){
        const int buf = t & 1;
        if (t + 1 < T){
            const float* An = Ap + (t + 1) * 16;
            const float* Wn = Wp + (t + 1) * 16;
            a0 = *(const float4*)(An);
            a1 = *(const float4*)(An + 4);
            b0 = *(const float4*)(Wn);
            b1 = *(const float4*)(Wn + 4);
        }

#pragma unroll
        for (int ks = 0; ks < 2; ks++){
            const int kk = ks * 8;
            uint32_t af[4][4], bf[4][2];
#pragma unroll
            for (int mt = 0; mt < 4; mt++){
                const int m = wm * 64 + mt * 16 + ml;
                af[mt][0] = As[buf][kk + cl][m];
                af[mt][1] = As[buf][kk + cl][m + 8];
                af[mt][2] = As[buf][kk + 4 + cl][m];
                af[mt][3] = As[buf][kk + 4 + cl][m + 8];
            }
#pragma unroll
            for (int nt = 0; nt < 4; nt++){
                const int n = wn * 32 + nt * 8 + ml;
                bf[nt][0] = Bs[buf][kk + cl][n];
                bf[nt][1] = Bs[buf][kk + 4 + cl][n];
            }
#pragma unroll
            for (int mt = 0; mt < 4; mt++)
#pragma unroll
                for (int nt = 0; nt < 4; nt++)
                    mma_16n8k8(acc[mt][nt], af[mt], bf[nt]);
        }

        if (t + 1 < T) STS_TILE(buf ^ 1);
        __syncthreads();
    }
#undef STS_TILE

    // epilogue
    const int rbase = blockIdx.y * 128 + wm * 64 + ml;
    const int cbase = blockIdx.x * 128 + wn * 32 + 2 * cl;
#pragma unroll
    for (int mt = 0; mt < 4; mt++){
#pragma unroll
        for (int nt = 0; nt < 4; nt++){
            const int row = rbase + mt * 16;
            const int col = cbase + nt * 8;
            float bx0 = 0.f, bx1 = 0.f;
            if (bias){ bx0 = bias[col]; bx1 = bias[col + 1]; }
            float v00 = acc[mt][nt][0] + bx0, v01 = acc[mt][nt][1] + bx1;
            float v10 = acc[mt][nt][2] + bx0, v11 = acc[mt][nt][3] + bx1;
            if (act){
                v00 = fmaxf(v00, 0.f); v01 = fmaxf(v01, 0.f);
                v10 = fmaxf(v10, 0.f); v11 = fmaxf(v11, 0.f);
            }
            float2 u0 = { v00, v01 }, u1 = { v10, v11 };
            *(float2*)&C[(size_t)row * ldc + col] = u0;
            *(float2*)&C[(size_t)(row + 8) * ldc + col] = u1;
        }
    }
}

// ---------------- per-head layernorm over DH=64 ----------------
__global__ void ln_head_kernel(float* __restrict__ x,
                               const float* __restrict__ g, const float* __restrict__ b,
                               int rows)
{
    int row = blockIdx.x * 8 + (threadIdx.x >> 5);
    int lane = threadIdx.x & 31;
    if (row >= rows) return;
    float* p = x + (size_t)row * 64;
    float v0 = p[lane], v1 = p[lane + 32];
    float s = v0 + v1;
#pragma unroll
    for (int off = 16; off; off >>= 1) s += __shfl_xor_sync(0xffffffffu, s, off);
    float mu = s * (1.f / 64.f);
    float d0 = v0 - mu, d1 = v1 - mu;
    float q = d0 * d0 + d1 * d1;
#pragma unroll
    for (int off = 16; off; off >>= 1) q += __shfl_xor_sync(0xffffffffu, q, off);
    float r = rsqrtf(q * (1.f / 64.f) + EPSF);
    p[lane]      = d0 * r * g[lane]      + b[lane];
    p[lane + 32] = d1 * r * g[lane + 32] + b[lane + 32];
}

// ---------------- block reduction helper ----------------
__device__ __forceinline__ float2 blockReduce2(float a, float b)
{
    __shared__ float sa[8], sb[8];
    int lane = threadIdx.x & 31, w = threadIdx.x >> 5;
#pragma unroll
    for (int off = 16; off; off >>= 1) {
        a += __shfl_xor_sync(0xffffffffu, a, off);
        b += __shfl_xor_sync(0xffffffffu, b, off);
    }
    __syncthreads();
    if (lane == 0) { sa[w] = a; sb[w] = b; }
    __syncthreads();
    float ra = 0.f, rb = 0.f;
#pragma unroll
    for (int i = 0; i < 8; i++) { ra += sa[i]; rb += sb[i]; }
    return make_float2(ra, rb);
}

// ---------------- layernorm over D=1024 (+optional residual) ----------------
__global__ void ln1024_kernel(const float* __restrict__ in, const float* __restrict__ res,
                              const float* __restrict__ g, const float* __restrict__ b,
                              float* __restrict__ out)
{
    int row = blockIdx.x, tid = threadIdx.x;
    size_t base = (size_t)row * 1024 + tid * 4;
    float4 v = *(const float4*)(in + base);
    float x[4] = { v.x, v.y, v.z, v.w };
    if (res) {
        float4 rv = *(const float4*)(res + base);
        x[0] += rv.x; x[1] += rv.y; x[2] += rv.z; x[3] += rv.w;
    }
    float sa = 0.f, sb = 0.f;
#pragma unroll
    for (int i = 0; i < 4; i++) { sa += x[i]; sb += x[i] * x[i]; }
    float2 r = blockReduce2(sa, sb);
    float mu = r.x * (1.f / 1024.f);
    float var = r.y * (1.f / 1024.f) - mu * mu;
    float rs = rsqrtf(var + EPSF);
    float4 g4 = *(const float4*)(g + tid * 4);
    float4 b4 = *(const float4*)(b + tid * 4);
    float4 o;
    o.x = (x[0] - mu) * rs * g4.x + b4.x;
    o.y = (x[1] - mu) * rs * g4.y + b4.y;
    o.z = (x[2] - mu) * rs * g4.z + b4.z;
    o.w = (x[3] - mu) * rs * g4.w + b4.w;
    *(float4*)(out + base) = o;
}

// ---------------- fused gate ----------------
__global__ void gate_kernel(const float* __restrict__ sp, const float* __restrict__ hp,
                            const float* __restrict__ bf,
                            const float* __restrict__ gg, const float* __restrict__ gb,
                            float* __restrict__ out)
{
    int row = blockIdx.x, tid = threadIdx.x;
    size_t base = (size_t)row * 1024 + tid * 4;
    float4 sv = *(const float4*)(sp + base);
    float4 hv = *(const float4*)(hp + base);
    float s[4] = { sv.x, sv.y, sv.z, sv.w };
    float h[4] = { hv.x, hv.y, hv.z, hv.w };

    float sa = 0.f, sb = 0.f;
#pragma unroll
    for (int i = 0; i < 4; i++) { sa += s[i]; sb += s[i] * s[i]; }
    float2 r = blockReduce2(sa, sb);
    float mus = r.x * (1.f / 1024.f);
    float rs = rsqrtf(r.y * (1.f / 1024.f) - mus * mus + EPSF);

    sa = 0.f; sb = 0.f;
#pragma unroll
    for (int i = 0; i < 4; i++) { sa += h[i]; sb += h[i] * h[i]; }
    r = blockReduce2(sa, sb);
    float muh = r.x * (1.f / 1024.f);
    float rh = rsqrtf(r.y * (1.f / 1024.f) - muh * muh + EPSF);

    float4 g4 = *(const float4*)(gg + tid * 4);
    float4 b4 = *(const float4*)(gb + tid * 4);
    float4 f4 = *(const float4*)(bf + tid * 4);
    float gA[4] = { g4.x, g4.y, g4.z, g4.w };
    float bA[4] = { b4.x, b4.y, b4.z, b4.w };
    float fA[4] = { f4.x, f4.y, f4.z, f4.w };

    float t[4];
    sa = 0.f; sb = 0.f;
#pragma unroll
    for (int i = 0; i < 4; i++) {
        float sf = (s[i] - mus) * rs * gA[i] + bA[i];
        float hf = (h[i] - muh) * rh * gA[i] + bA[i];
        float f = 1.f / (1.f + expf(-(sf + hf + fA[i])));
        float ti = f * sf + (1.f - f) * hf;
        t[i] = ti; sa += ti; sb += ti * ti;
    }
    r = blockReduce2(sa, sb);
    float mut = r.x * (1.f / 1024.f);
    float rt = rsqrtf(r.y * (1.f / 1024.f) - mut * mut + EPSF);
    float4 o;
    o.x = (t[0] - mut) * rt * gA[0] + bA[0];
    o.y = (t[1] - mut) * rt * gA[1] + bA[1];
    o.z = (t[2] - mut) * rt * gA[2] + bA[2];
    o.w = (t[3] - mut) * rt * gA[3] + bA[3];
    *(float4*)(out + base) = o;
}

// ---------------- softmax column-sum over materialized scores ----------------
// colsum[n,h,l] += softmax_k(E[n,h,q,:]/32 + masks + dist)[l], summed over q.
__global__ void __launch_bounds__(256)
attn_soft(const float* __restrict__ E, const float* __restrict__ mask,
          float* __restrict__ colsum)
{
    __shared__ float cs[1024];
    __shared__ float msk[1024];
    const int tid = threadIdx.x, lane = tid & 31, w = tid >> 5;
    const int n = blockIdx.z, h = blockIdx.y;
    const int q = blockIdx.x * 8 + w;

    for (int i = tid; i < 1024; i += 256) { cs[i] = 0.f; msk[i] = mask[n * Sn + i]; }
    __syncthreads();

    const float mq = msk[q];
    const float* e = E + ((size_t)(n * Hn + h) * Sn + q) * Sn;
    float s[32];
#pragma unroll
    for (int i = 0; i < 8; i++){
        int kg = i * 128 + lane * 4;
        float4 v = *(const float4*)(e + kg);
        float vv[4] = { v.x, v.y, v.z, v.w };
#pragma unroll
        for (int j = 0; j < 4; j++){
            int kk = kg + j;
            float fm = mq * msk[kk] * ((q > kk) ? 0.f : NEGF);
            float dist = -fabsf((float)(q - kk));
            s[i * 4 + j] = (vv[j] * 0.03125f + fm) + dist;
        }
    }
    float m = s[0];
#pragma unroll
    for (int i = 1; i < 32; i++) m = fmaxf(m, s[i]);
#pragma unroll
    for (int o = 16; o; o >>= 1) m = fmaxf(m, __shfl_xor_sync(0xffffffffu, m, o));
    float Z = 0.f;
#pragma unroll
    for (int i = 0; i < 32; i++){
        float d = s[i] - m;
        s[i] = (d > -25.f) ? __expf(d) : 0.f;
        Z += s[i];
    }
#pragma unroll
    for (int o = 16; o; o >>= 1) Z += __shfl_xor_sync(0xffffffffu, Z, o);
    float iz = 1.f / Z;
#pragma unroll
    for (int i = 0; i < 32; i++){
        if (s[i] != 0.f){
            int kk = (i >> 2) * 128 + lane * 4 + (i & 3);
            atomicAdd(&cs[kk], s[i] * iz);
        }
    }
    __syncthreads();
    float* dst = colsum + (size_t)(n * Hn + h) * Sn;
    for (int i = tid; i < 1024; i += 256)
        if (cs[i] != 0.f) atomicAdd(&dst[i], cs[i]);
}

// ---------------- elementwise: attn_out = v_ln * colsum ----------------
__global__ void scale_v_kernel(const float* __restrict__ vln, const float* __restrict__ colsum,
                               float* __restrict__ out)
{
    int idx = blockIdx.x * blockDim.x + threadIdx.x;
    int token = idx >> 10;
    int n = token >> 10;
    int sidx = token & 1023;
    int h = (idx >> 6) & 15;
    out[idx] = vln[idx] * colsum[(((size_t)n * Hn + h) << 10) + sidx];
}

__global__ void zero_kernel(float* __restrict__ p, int n)
{
    int i = blockIdx.x * blockDim.x + threadIdx.x;
    if (i < n) p[i] = 0.f;
}

// ---------------- host orchestration ----------------
extern "C" void kernel_launch(void* const* d_in, const int* in_sizes, int n_in,
                              void* d_out, int out_size)
{
    const float* x     = (const float*)d_in[0];
    const float* mask  = (const float*)d_in[1];
    const float* Wq    = (const float*)d_in[2];
    const float* Wk    = (const float*)d_in[3];
    const float* Wv    = (const float*)d_in[4];
    const float* ln1g  = (const float*)d_in[5];
    const float* ln1b  = (const float*)d_in[6];
    const float* Wo    = (const float*)d_in[7];
    const float* bo    = (const float*)d_in[8];
    const float* ln2g  = (const float*)d_in[9];
    const float* ln2b  = (const float*)d_in[10];
    const float* Ws    = (const float*)d_in[11];
    const float* Wh    = (const float*)d_in[12];
    const float* bf    = (const float*)d_in[13];
    const float* lnfgg = (const float*)d_in[14];
    const float* lnfgb = (const float*)d_in[15];
    const float* Wp1   = (const float*)d_in[16];
    const float* bp1   = (const float*)d_in[17];
    const float* Wp2   = (const float*)d_in[18];
    const float* bp2   = (const float*)d_in[19];
    const float* lnffg = (const float*)d_in[20];
    const float* lnffb = (const float*)d_in[21];
    float* out = (float*)d_out;

    float *q, *k, *v, *t1, *t2, *t3, *ff, *cs, *sc;
    cudaGetSymbolAddress((void**)&q,  g_q);
    cudaGetSymbolAddress((void**)&k,  g_k);
    cudaGetSymbolAddress((void**)&v,  g_v);
    cudaGetSymbolAddress((void**)&t1, g_t1);
    cudaGetSymbolAddress((void**)&t2, g_t2);
    cudaGetSymbolAddress((void**)&t3, g_t3);
    cudaGetSymbolAddress((void**)&ff, g_ff);
    cudaGetSymbolAddress((void**)&cs, g_cs);
    cudaGetSymbolAddress((void**)&sc, g_sc);

    dim3 gD(8, 32, 1);     // N=1024, M=4096
    dim3 gF1(32, 32, 1);   // N=4096, M=4096
    dim3 gF2(8, 32, 1);    // N=1024, M=4096 (K=4096)
    dim3 gQK(8, 8, 64);    // per (n,h): 1024x1024, K=64

    // QKV projections (tf32 mma.sync tensor cores)
    gemm_mma<<<gD, 256>>>(x, Wq, nullptr, q, Dn, Dn, Dn, Dn, 0, 1, 0,0,0,0,0,0);
    gemm_mma<<<gD, 256>>>(x, Wk, nullptr, k, Dn, Dn, Dn, Dn, 0, 1, 0,0,0,0,0,0);
    gemm_mma<<<gD, 256>>>(x, Wv, nullptr, v, Dn, Dn, Dn, Dn, 0, 1, 0,0,0,0,0,0);

    // per-head LN of q,k,v (in place)
    ln_head_kernel<<<TOK * Hn / 8, 256>>>(q, ln1g, ln1b, TOK * Hn);
    ln_head_kernel<<<TOK * Hn / 8, 256>>>(k, ln1g, ln1b, TOK * Hn);
    ln_head_kernel<<<TOK * Hn / 8, 256>>>(v, ln1g, ln1b, TOK * Hn);

    // E = Qln @ Kln^T per (n,h)  (batched tf32 GEMM, K=64)
    gemm_mma<<<gQK, 256>>>(q, k, nullptr, sc, DHn, Dn, Dn, Sn, 0, Hn,
                           (long long)Sn * Dn, 64,
                           (long long)Sn * Dn, 64,
                           (long long)Hn * Sn * Sn, (long long)Sn * Sn);

    // softmax column sums (exp-skipping)
    zero_kernel<<<(Bn * Hn * Sn) / 256, 256>>>(cs, Bn * Hn * Sn);
    attn_soft<<<dim3(Sn / 8, Hn, Bn), 256>>>(sc, mask, cs);

    // attn_out = v_ln * colsum  (into q buffer)
    scale_v_kernel<<<(TOK * Dn) / 256, 256>>>(v, cs, q);

    // output projection + LN -> h (t1)
    gemm_mma<<<gD, 256>>>(q, Wo, bo, t1, Dn, Dn, Dn, Dn, 0, 1, 0,0,0,0,0,0);
    ln1024_kernel<<<TOK, 256>>>(t1, nullptr, ln2g, ln2b, t1);

    // fusion gate
    gemm_mma<<<gD, 256>>>(x,  Ws, nullptr, t2, Dn, Dn, Dn, Dn, 0, 1, 0,0,0,0,0,0);
    gemm_mma<<<gD, 256>>>(t1, Wh, nullptr, t3, Dn, Dn, Dn, Dn, 0, 1, 0,0,0,0,0,0);
    gate_kernel<<<TOK, 256>>>(t2, t3, bf, lnfgg, lnfgb, k);   // g -> k buffer

    // FFN
    gemm_mma<<<gF1, 256>>>(k, Wp1, bp1, ff, Dn, Dn, Dn, DFFn, 1, 1, 0,0,0,0,0,0);
    gemm_mma<<<gF2, 256>>>(ff, Wp2, bp2, t3, DFFn, DFFn, DFFn, Dn, 0, 1, 0,0,0,0,0,0);

    // final residual + LN
    ln1024_kernel<<<TOK, 256>>>(t3, k, lnffg, lnffb, out);
}